// round 17
// baseline (speedup 1.0000x reference)
#include <cuda_runtime.h>
#include <cstdint>

#define TT   1024
#define BSZ  64
#define G4   1024
#define TBH  (TT*BSZ*256)
#define BH   (BSZ*256)
#define NCTA 128             // 16 clusters x 8 CTAs
#define CLU  8
#define NTHR 512

typedef unsigned long long ull;

// Scratch (device globals: no runtime allocation allowed)
__device__ float g_Z[(size_t)TT * BSZ * G4];   // [t][b][gate*256+u]  (256 MB)
__device__ int   g_done[512];                  // per-y-tile completion counters

#define FMA_F32X2(d, a, b, c) \
    asm("fma.rn.f32x2 %0, %1, %2, %3;" : "=l"(d) : "l"(a), "l"(b), "l"(c))
#define ADD_F32X2(d, a, b) \
    asm("add.rn.f32x2 %0, %1, %2;" : "=l"(d) : "l"(a), "l"(b))
#define PACK2(d, lo, hi) \
    asm("mov.b64 %0, {%1, %2};" : "=l"(d) : "f"(lo), "f"(hi))
#define UNPACK2(lo, hi, s) \
    asm("mov.b64 {%0, %1}, %2;" : "=f"(lo), "=f"(hi) : "l"(s))

__global__ void reset_kernel() {
    g_done[threadIdx.x] = 0;
}

// ---------------------------------------------------------------------------
// Phase 1: Z GEMM, concurrent on stream s2 (free SMs); per-y-tile signal.
// ---------------------------------------------------------------------------
__global__ __launch_bounds__(256, 2)
void proj_kernel(const float* __restrict__ x,
                 const float* __restrict__ Wf, const float* __restrict__ bf,
                 const float* __restrict__ Wi, const float* __restrict__ bi,
                 const float* __restrict__ Wg, const float* __restrict__ bg,
                 const float* __restrict__ Wo, const float* __restrict__ bo)
{
    __shared__ float As[16 * 132];
    __shared__ float Bs[16 * 132];

    const int tid = threadIdx.x;
    const int tx  = tid & 15;
    const int ty  = tid >> 4;
    const int bm    = blockIdx.y * 128;
    const int gate  = blockIdx.x >> 1;
    const int ucol0 = (blockIdx.x & 1) * 128;

    const float* W    = (gate == 0) ? Wf : (gate == 1) ? Wi : (gate == 2) ? Wg : Wo;
    const float* bias = (gate == 0) ? bf : (gate == 1) ? bi : (gate == 2) ? bg : bo;

    float acc[8][8];
#pragma unroll
    for (int i = 0; i < 8; i++)
#pragma unroll
        for (int j = 0; j < 8; j++) acc[i][j] = 0.f;

    for (int k0 = 0; k0 < 256; k0 += 16) {
#pragma unroll
        for (int it = 0; it < 2; it++) {
            int f4  = tid + it * 256;
            int row = f4 >> 2;
            int kc  = (f4 & 3) << 2;
            float4 av = *(const float4*)(x + (size_t)(bm + row) * 256 + k0 + kc);
            As[(kc + 0) * 132 + row] = av.x;
            As[(kc + 1) * 132 + row] = av.y;
            As[(kc + 2) * 132 + row] = av.z;
            As[(kc + 3) * 132 + row] = av.w;
            float4 bv = *(const float4*)(W + (size_t)(ucol0 + row) * 512 + k0 + kc);
            Bs[(kc + 0) * 132 + row] = bv.x;
            Bs[(kc + 1) * 132 + row] = bv.y;
            Bs[(kc + 2) * 132 + row] = bv.z;
            Bs[(kc + 3) * 132 + row] = bv.w;
        }
        __syncthreads();
#pragma unroll
        for (int kk = 0; kk < 16; kk++) {
            float4 a0 = *(const float4*)&As[kk * 132 + ty * 8];
            float4 a1 = *(const float4*)&As[kk * 132 + ty * 8 + 4];
            float4 b0 = *(const float4*)&Bs[kk * 132 + tx * 8];
            float4 b1 = *(const float4*)&Bs[kk * 132 + tx * 8 + 4];
            float a[8] = {a0.x, a0.y, a0.z, a0.w, a1.x, a1.y, a1.z, a1.w};
            float b[8] = {b0.x, b0.y, b0.z, b0.w, b1.x, b1.y, b1.z, b1.w};
#pragma unroll
            for (int i = 0; i < 8; i++)
#pragma unroll
                for (int j = 0; j < 8; j++) acc[i][j] += a[i] * b[j];
        }
        __syncthreads();
    }

    float4 q0 = *(const float4*)(bias + ucol0 + tx * 8);
    float4 q1 = *(const float4*)(bias + ucol0 + tx * 8 + 4);
    float bb[8] = {q0.x, q0.y, q0.z, q0.w, q1.x, q1.y, q1.z, q1.w};

#pragma unroll
    for (int i = 0; i < 8; i++) {
        size_t m  = (size_t)(bm + ty * 8 + i);
        float* zp = g_Z + m * 1024 + gate * 256 + ucol0 + tx * 8;
        float4 v0 = {acc[i][0] + bb[0], acc[i][1] + bb[1], acc[i][2] + bb[2], acc[i][3] + bb[3]};
        float4 v1 = {acc[i][4] + bb[4], acc[i][5] + bb[5], acc[i][6] + bb[6], acc[i][7] + bb[7]};
        *(float4*)zp       = v0;
        *(float4*)(zp + 4) = v1;
    }

    __threadfence();
    __syncthreads();
    if (tid == 0) atomicAdd(&g_done[blockIdx.y], 1);
}

// ---------------------------------------------------------------------------
// Phase 2: cluster recurrence, 4-WAY source-split barriers.
// mbar[q] (count 2) <- ranks 2q,2q+1; warp kq waits only mbar[kq] (the exact
// two source CTAs of its k-range). Remote h-window addresses hoisted via one
// mapa per rank; double buffer indexed by +4096B after translation. Pushes
// paired: even lane pushes {h_even, h_odd} as one b64 per rank.
// ---------------------------------------------------------------------------
__device__ __forceinline__ float sig_(float v)  { return __fdividef(1.f, 1.f + __expf(-v)); }
__device__ __forceinline__ float tanh_(float v) { return __fdividef(2.f, 1.f + __expf(-2.f * v)) - 1.f; }

__device__ __forceinline__ uint32_t smem_u32(const void* p) {
    uint32_t a;
    asm("{ .reg .u64 t; cvta.to.shared.u64 t, %1; cvt.u32.u64 %0, t; }"
        : "=r"(a) : "l"(p));
    return a;
}

__device__ __forceinline__ uint32_t mapa_(uint32_t laddr, int rank) {
    uint32_t ra;
    asm("mapa.shared::cluster.u32 %0, %1, %2;" : "=r"(ra) : "r"(laddr), "r"(rank));
    return ra;
}

__device__ __forceinline__ void st_cluster_b64(uint32_t raddr, ull v) {
    asm volatile("st.shared::cluster.b64 [%0], %1;" :: "r"(raddr), "l"(v));
}

__device__ __forceinline__ void remote_arrive(uint32_t bar_laddr, int rank) {
    asm volatile(
        "{ .reg .b32 ra;\n\t"
        "mapa.shared::cluster.u32 ra, %0, %1;\n\t"
        "mbarrier.arrive.release.cluster.shared::cluster.b64 _, [ra]; }"
        :: "r"(bar_laddr), "r"(rank) : "memory");
}

__device__ __forceinline__ void bar_wait(uint32_t bar_laddr, unsigned parity) {
    asm volatile(
        "{ .reg .pred P;\n\t"
        "W_%=:\n\t"
        "mbarrier.try_wait.parity.acquire.cluster.shared::cta.b64 P, [%0], %1, 0x989680;\n\t"
        "@!P bra W_%=;\n\t"
        "}"
        :: "r"(bar_laddr), "r"(parity) : "memory");
}

__device__ __forceinline__ int ld_acq(const int* p) {
    int v;
    asm volatile("ld.acquire.gpu.global.s32 %0, [%1];" : "=r"(v) : "l"(p) : "memory");
    return v;
}

#define CLUSTER_SYNC_() do { \
    asm volatile("barrier.cluster.arrive.aligned;" ::: "memory"); \
    asm volatile("barrier.cluster.wait.aligned;"   ::: "memory"); \
} while (0)

__global__ __launch_bounds__(NTHR, 1)
void lstm_kernel(const float* __restrict__ Wf, const float* __restrict__ Wi,
                 const float* __restrict__ Wg, const float* __restrict__ Wo,
                 float* __restrict__ out)
{
    __shared__ float hs[2][4][256];     // [buf][bq][k]  (8KB; buf stride 4096B)
    __shared__ float pre4[4][4][128];   // [bq][kq][col] (8KB)
    __shared__ ull   mbar[4];           // class q <- ranks 2q, 2q+1

    const int tid  = threadIdx.x;
    const int lane = tid & 31;
    const int w    = tid >> 5;
    const int kq   = w >> 2;            // k-range [64kq, 64kq+64)
    const int cg   = w & 3;
    const int lc   = cg * 32 + lane;    // local col 0..127

    uint32_t rank;
    asm("mov.u32 %0, %%cluster_ctarank;" : "=r"(rank));
    const int cid = blockIdx.x >> 3;
    const int b0  = cid * 4;
    const uint32_t mb_my   = smem_u32(&mbar[rank >> 1]);  // class I signal
    const uint32_t mb_wait = smem_u32(&mbar[kq]);         // class I consume

    // ---- recurrent weights: this thread's col, k in [64kq, 64kq+64) ----
    const int uu = lc >> 2;
    const int gt = lc & 3;
    const float* Ws[4] = {Wf, Wi, Wg, Wo};
    const ull* wrow = (const ull*)(Ws[gt] + (size_t)(rank * 32 + uu) * 512 + 256 + kq * 64);
    ull wk[32];
#pragma unroll
    for (int j = 0; j < 32; j++) wk[j] = wrow[j];

    // zero h buffers; init 4 split barriers (2 arrivals each)
    for (int i = tid; i < 2 * 4 * 256; i += NTHR) ((float*)hs)[i] = 0.f;
    if (tid < 4) {
        uint32_t mb = smem_u32(&mbar[tid]);
        asm volatile("mbarrier.init.shared.b64 [%0], %1;" :: "r"(mb), "r"(2) : "memory");
    }

    // epilogue identity (threads 0..127): bq = tid>>5, uue = tid&31
    const int bq_e  = tid >> 5;
    const int uu_e  = tid & 31;
    const int bg_e  = b0 + bq_e;
    const int ug_e  = (int)rank * 32 + uu_e;
    float cstate = 0.f;
    int have_y = -1;

    // hoisted remote addresses: pair base = hs[0][bq_e][ug_e] (even lanes)
    uint32_t ra[CLU];
    {
        uint32_t hpair = smem_u32(&hs[0][bq_e][ug_e]);
#pragma unroll
        for (int r = 0; r < CLU; r++) ra[r] = mapa_(hpair, r);
    }

    CLUSTER_SYNC_();   // hs zeros + barrier init visible cluster-wide

    for (int t = 0; t < TT; t++) {
        // ---- guarded Z prefetch (proj runs concurrently) ----
        float z0, z1, z2, z3;
        if (tid < 128) {
            const int yneed = t >> 1;
            if (yneed > have_y) {
                while (ld_acq(&g_done[yneed]) < 8) {}
                have_y = yneed;
            }
            const float* zr = g_Z + ((size_t)t * 64 + bg_e) * 1024 + ug_e;
            z0 = __ldcs(zr);
            z1 = __ldcs(zr + 256);
            z2 = __ldcs(zr + 512);
            z3 = __ldcs(zr + 768);
        }

        // ---- wait ONLY for the 2 source CTAs this warp consumes ----
        if (t > 0) bar_wait(mb_wait, (unsigned)((t - 1) & 1));

        // ---- recurrent GEMM: 4 batches, this thread's col, 64 k's ----
        const int buf = t & 1;
#pragma unroll
        for (int bq = 0; bq < 4; bq++) {
            const ulonglong2* hp2 = (const ulonglong2*)&hs[buf][bq][kq * 64]; // 16 ull2
            ull a0 = 0ull, a1 = 0ull;
#pragma unroll
            for (int j = 0; j < 16; j++) {
                ulonglong2 hv = hp2[j];
                FMA_F32X2(a0, wk[2 * j + 0], hv.x, a0);
                FMA_F32X2(a1, wk[2 * j + 1], hv.y, a1);
            }
            ADD_F32X2(a0, a0, a1);
            float lo, hi; UNPACK2(lo, hi, a0);
            pre4[bq][kq][lc] = lo + hi;
        }
        __syncthreads();

        // ---- epilogue: 128 threads, one (batch, unit) each ----
        if (tid < 128) {
            float pf = 0.f, pi = 0.f, pg = 0.f, po = 0.f;
#pragma unroll
            for (int q = 0; q < 4; q++) {
                float4 s = *(const float4*)&pre4[bq_e][q][uu_e * 4];
                pf += s.x; pi += s.y; pg += s.z; po += s.w;
            }
            float fg = sig_ (pf + z0);
            float ig = sig_ (pi + z1);
            float gg = tanh_(pg + z2);
            float og = sig_ (po + z3);
            cstate = fg * cstate + ig * gg;
            float h = og * tanh_(cstate);

            // paired push: even lane sends {h_even, h_odd} as one b64
            float hn = __shfl_down_sync(0xffffffffu, h, 1);
            if ((lane & 1) == 0) {
                ull hp; PACK2(hp, h, hn);
                const uint32_t off = (uint32_t)((buf ^ 1) * 4096);
#pragma unroll
                for (int r = 0; r < CLU; r++) st_cluster_b64(ra[r] + off, hp);
            }

            out[((size_t)t * 64 + bg_e) * 256 + ug_e] = h;
            if (t == TT - 1) {
                out[TBH + bg_e * 256 + ug_e]      = h;
                out[TBH + BH + bg_e * 256 + ug_e] = cstate;
            }
        }

        // pushes ordered before arrives via syncthreads; threads 0..7
        // release-arrive in PARALLEL on their class, one dest CTA each.
        __syncthreads();
        if (tid < CLU) remote_arrive(mb_my, tid);
    }

    // no CTA exits while peers may still push/arrive into its SMEM
    CLUSTER_SYNC_();
}

// ---------------------------------------------------------------------------
// Launch: reset -> fork (proj on s2 || lstm on capture stream) -> join.
// ---------------------------------------------------------------------------
extern "C" void kernel_launch(void* const* d_in, const int* in_sizes, int n_in,
                              void* d_out, int out_size)
{
    const float* x  = (const float*)d_in[0];
    const float* Wf = (const float*)d_in[1];
    const float* bf = (const float*)d_in[2];
    const float* Wi = (const float*)d_in[3];
    const float* bi = (const float*)d_in[4];
    const float* Wg = (const float*)d_in[5];
    const float* bg = (const float*)d_in[6];
    const float* Wo = (const float*)d_in[7];
    const float* bo = (const float*)d_in[8];
    float* out = (float*)d_out;

    static cudaStream_t s2;
    static cudaEvent_t  evA, evB;
    static bool init = false;
    if (!init) {
        cudaStreamCreateWithFlags(&s2, cudaStreamNonBlocking);
        cudaEventCreateWithFlags(&evA, cudaEventDisableTiming);
        cudaEventCreateWithFlags(&evB, cudaEventDisableTiming);
        init = true;
    }

    reset_kernel<<<1, 512>>>();

    cudaEventRecord(evA, 0);
    cudaStreamWaitEvent(s2, evA, 0);

    proj_kernel<<<dim3(8, 512), 256, 0, s2>>>(x, Wf, bf, Wi, bi, Wg, bg, Wo, bo);

    cudaLaunchConfig_t cfg = {};
    cfg.gridDim  = dim3(NCTA, 1, 1);
    cfg.blockDim = dim3(NTHR, 1, 1);
    cfg.dynamicSmemBytes = 0;
    cudaLaunchAttribute attrs[1];
    attrs[0].id = cudaLaunchAttributeClusterDimension;
    attrs[0].val.clusterDim.x = CLU;
    attrs[0].val.clusterDim.y = 1;
    attrs[0].val.clusterDim.z = 1;
    cfg.attrs = attrs;
    cfg.numAttrs = 1;
    cudaLaunchKernelEx(&cfg, lstm_kernel, Wf, Wi, Wg, Wo, out);

    cudaEventRecord(evB, s2);
    cudaStreamWaitEvent(0, evB, 0);
}